// round 1
// baseline (speedup 1.0000x reference)
#include <cuda_runtime.h>

#define NNODE 50000
#define NEDGE 800000
#define DIM   128
#define NQ_NODE (NNODE/4)   // 12500
#define NQ_EDGE (NEDGE/4)   // 200000
#define EPS_LN 1e-5f

// Scratch (device globals: no allocations allowed)
__device__ float g_Pa[NNODE*DIM];   // x @ ew1[0:128]   + eb1
__device__ float g_Pb[NNODE*DIM];   // x @ ew1[128:256]
__device__ float g_Pn[NNODE*DIM];   // x @ nw1[0:128]   + nb1
__device__ float g_agg[NNODE*DIM];  // segment_sum(edge_attr_new, j)

__device__ __forceinline__ float silu_f(float v) {
    return v * (1.0f / (1.0f + __expf(-v)));
}
__device__ __forceinline__ float4 silu4(float4 v) {
    return make_float4(silu_f(v.x), silu_f(v.y), silu_f(v.z), silu_f(v.w));
}

// One 128->128 dense layer step for 4 rows held in smem (myrow: 4 x 128 floats).
// Lane owns output cols [4*lane, 4*lane+4). acc must be pre-initialized (bias).
__device__ __forceinline__ void layer128(const float* __restrict__ sW,
                                         const float* __restrict__ myrow,
                                         int lane, float4 acc[4]) {
    #pragma unroll 4
    for (int k = 0; k < 128; k++) {
        float4 w = ((const float4*)sW)[k * 32 + lane];
        float e0 = myrow[k];
        float e1 = myrow[128 + k];
        float e2 = myrow[256 + k];
        float e3 = myrow[384 + k];
        acc[0].x = fmaf(e0, w.x, acc[0].x); acc[0].y = fmaf(e0, w.y, acc[0].y);
        acc[0].z = fmaf(e0, w.z, acc[0].z); acc[0].w = fmaf(e0, w.w, acc[0].w);
        acc[1].x = fmaf(e1, w.x, acc[1].x); acc[1].y = fmaf(e1, w.y, acc[1].y);
        acc[1].z = fmaf(e1, w.z, acc[1].z); acc[1].w = fmaf(e1, w.w, acc[1].w);
        acc[2].x = fmaf(e2, w.x, acc[2].x); acc[2].y = fmaf(e2, w.y, acc[2].y);
        acc[2].z = fmaf(e2, w.z, acc[2].z); acc[2].w = fmaf(e2, w.w, acc[2].w);
        acc[3].x = fmaf(e3, w.x, acc[3].x); acc[3].y = fmaf(e3, w.y, acc[3].y);
        acc[3].z = fmaf(e3, w.z, acc[3].z); acc[3].w = fmaf(e3, w.w, acc[3].w);
    }
}

// Warp-wide allreduce of per-row sum / sumsq for 4 rows.
__device__ __forceinline__ void ln_reduce(float s[4], float ss[4]) {
    #pragma unroll
    for (int o = 16; o > 0; o >>= 1) {
        #pragma unroll
        for (int t = 0; t < 4; t++) {
            s[t]  += __shfl_xor_sync(0xffffffffu, s[t],  o);
            ss[t] += __shfl_xor_sync(0xffffffffu, ss[t], o);
        }
    }
}

// ---------------------------------------------------------------------------
// Kernel 1: per-node projections Pa = x@W1a + eb1, Pb = x@W1b, Pn = x@nw1a + nb1
// ---------------------------------------------------------------------------
__global__ void __launch_bounds__(512, 1) precompute_kernel(
    const float* __restrict__ x,
    const float* __restrict__ ew1, const float* __restrict__ eb1,
    const float* __restrict__ nw1, const float* __restrict__ nb1)
{
    extern __shared__ float sm[];
    float* sWa = sm;               // 16384
    float* sWb = sWa + 16384;      // 16384
    float* sWn = sWb + 16384;      // 16384
    float* sB  = sWn + 16384;      // 256: eb1 | nb1
    float* sRows = sB + 256;       // 16 warps * 512

    for (int idx = threadIdx.x; idx < 16384; idx += 512) {
        sWa[idx] = ew1[idx];               // rows 0..127
        sWb[idx] = ew1[16384 + idx];       // rows 128..255
        sWn[idx] = nw1[idx];               // rows 0..127
    }
    if (threadIdx.x < 128) {
        sB[threadIdx.x]       = eb1[threadIdx.x];
        sB[128 + threadIdx.x] = nb1[threadIdx.x];
    }
    __syncthreads();

    const int warp = threadIdx.x >> 5, lane = threadIdx.x & 31;
    const int gwarp  = blockIdx.x * 16 + warp;
    const int nwarps = gridDim.x * 16;
    float* myrow = sRows + warp * 512;

    float4 eb1v = ((const float4*)sB)[lane];
    float4 nb1v = ((const float4*)(sB + 128))[lane];

    for (int q = gwarp; q < NQ_NODE; q += nwarps) {
        const int n0 = q * 4;
        const float4* src = (const float4*)(x + (size_t)n0 * DIM);
        float4* rows4 = (float4*)myrow;
        #pragma unroll
        for (int t = lane; t < 128; t += 32) rows4[t] = src[t];
        __syncwarp();

        float4 aA[4], aB[4], aN[4];
        #pragma unroll
        for (int t = 0; t < 4; t++) {
            aA[t] = eb1v; aB[t] = make_float4(0.f, 0.f, 0.f, 0.f); aN[t] = nb1v;
        }
        #pragma unroll 2
        for (int k = 0; k < 128; k++) {
            float4 wa = ((const float4*)sWa)[k * 32 + lane];
            float4 wb = ((const float4*)sWb)[k * 32 + lane];
            float4 wn = ((const float4*)sWn)[k * 32 + lane];
            #pragma unroll
            for (int t = 0; t < 4; t++) {
                float e = myrow[t * 128 + k];
                aA[t].x = fmaf(e, wa.x, aA[t].x); aA[t].y = fmaf(e, wa.y, aA[t].y);
                aA[t].z = fmaf(e, wa.z, aA[t].z); aA[t].w = fmaf(e, wa.w, aA[t].w);
                aB[t].x = fmaf(e, wb.x, aB[t].x); aB[t].y = fmaf(e, wb.y, aB[t].y);
                aB[t].z = fmaf(e, wb.z, aB[t].z); aB[t].w = fmaf(e, wb.w, aB[t].w);
                aN[t].x = fmaf(e, wn.x, aN[t].x); aN[t].y = fmaf(e, wn.y, aN[t].y);
                aN[t].z = fmaf(e, wn.z, aN[t].z); aN[t].w = fmaf(e, wn.w, aN[t].w);
            }
        }
        #pragma unroll
        for (int t = 0; t < 4; t++) {
            ((float4*)(g_Pa + (size_t)(n0 + t) * DIM))[lane] = aA[t];
            ((float4*)(g_Pb + (size_t)(n0 + t) * DIM))[lane] = aB[t];
            ((float4*)(g_Pn + (size_t)(n0 + t) * DIM))[lane] = aN[t];
        }
        __syncwarp();
    }
}

// ---------------------------------------------------------------------------
// Kernel 2: edge processor. h1 = silu(Pa[i]+Pb[j]+ea@W1c); h2; m; LN; residual;
// writes edge_attr_new and scatter-adds it into g_agg[j].
// ---------------------------------------------------------------------------
__global__ void __launch_bounds__(512, 1) edge_kernel(
    const int*   __restrict__ ei,     // [2, E]
    const float* __restrict__ ea,     // [E, 128]
    const float* __restrict__ ew1,    // [384, 128] (use rows 256..383)
    const float* __restrict__ ew2,
    const float* __restrict__ ew3,
    const float* __restrict__ eb2,
    const float* __restrict__ eb3,
    const float* __restrict__ elg,
    const float* __restrict__ elb,
    float* __restrict__ outE)         // [E, 128]
{
    extern __shared__ float sm[];
    float* sW1 = sm;               // W1c
    float* sW2 = sW1 + 16384;
    float* sW3 = sW2 + 16384;
    float* sB  = sW3 + 16384;      // eb2 | eb3 | gamma | beta
    float* sRows = sB + 512;

    for (int idx = threadIdx.x; idx < 16384; idx += 512) {
        sW1[idx] = ew1[32768 + idx];
        sW2[idx] = ew2[idx];
        sW3[idx] = ew3[idx];
    }
    if (threadIdx.x < 128) {
        int c = threadIdx.x;
        sB[c] = eb2[c]; sB[128 + c] = eb3[c]; sB[256 + c] = elg[c]; sB[384 + c] = elb[c];
    }
    __syncthreads();

    const int warp = threadIdx.x >> 5, lane = threadIdx.x & 31;
    const int gwarp  = blockIdx.x * 16 + warp;
    const int nwarps = gridDim.x * 16;
    float* myrow = sRows + warp * 512;

    float4 b2v = ((const float4*)sB)[lane];
    float4 b3v = ((const float4*)(sB + 128))[lane];
    float4 gv  = ((const float4*)(sB + 256))[lane];
    float4 bv  = ((const float4*)(sB + 384))[lane];

    for (int q = gwarp; q < NQ_EDGE; q += nwarps) {
        const int e0 = q * 4;
        int iq[4], jq[4];
        #pragma unroll
        for (int t = 0; t < 4; t++) {
            iq[t] = ei[e0 + t];
            jq[t] = ei[NEDGE + e0 + t];
        }
        // stage 4 contiguous edge_attr rows into smem
        const float4* src = (const float4*)(ea + (size_t)e0 * DIM);
        float4* rows4 = (float4*)myrow;
        #pragma unroll
        for (int t = lane; t < 128; t += 32) rows4[t] = src[t];
        __syncwarp();

        float4 resid[4];
        float4 acc[4];
        #pragma unroll
        for (int t = 0; t < 4; t++) {
            resid[t] = rows4[t * 32 + lane];
            float4 pa = ((const float4*)(g_Pa + (size_t)iq[t] * DIM))[lane];
            float4 pb = ((const float4*)(g_Pb + (size_t)jq[t] * DIM))[lane];
            acc[t] = make_float4(pa.x + pb.x, pa.y + pb.y, pa.z + pb.z, pa.w + pb.w);
        }

        layer128(sW1, myrow, lane, acc);              // + ea @ W1c (bias in Pa)
        __syncwarp();
        #pragma unroll
        for (int t = 0; t < 4; t++) rows4[t * 32 + lane] = silu4(acc[t]);
        __syncwarp();

        #pragma unroll
        for (int t = 0; t < 4; t++) acc[t] = b2v;
        layer128(sW2, myrow, lane, acc);
        __syncwarp();
        #pragma unroll
        for (int t = 0; t < 4; t++) rows4[t * 32 + lane] = silu4(acc[t]);
        __syncwarp();

        #pragma unroll
        for (int t = 0; t < 4; t++) acc[t] = b3v;
        layer128(sW3, myrow, lane, acc);

        // LayerNorm per row + residual + scatter
        float s[4], ss[4];
        #pragma unroll
        for (int t = 0; t < 4; t++) {
            float4 m = acc[t];
            s[t]  = m.x + m.y + m.z + m.w;
            ss[t] = m.x * m.x + m.y * m.y + m.z * m.z + m.w * m.w;
        }
        ln_reduce(s, ss);
        #pragma unroll
        for (int t = 0; t < 4; t++) {
            float mean = s[t] * (1.0f / 128.0f);
            float var  = ss[t] * (1.0f / 128.0f) - mean * mean;
            float inv  = rsqrtf(var + EPS_LN);
            float4 m = acc[t];
            float4 o;
            o.x = resid[t].x + (m.x - mean) * inv * gv.x + bv.x;
            o.y = resid[t].y + (m.y - mean) * inv * gv.y + bv.y;
            o.z = resid[t].z + (m.z - mean) * inv * gv.z + bv.z;
            o.w = resid[t].w + (m.w - mean) * inv * gv.w + bv.w;
            ((float4*)(outE + (size_t)(e0 + t) * DIM))[lane] = o;
            float* ag = g_agg + (size_t)jq[t] * DIM + 4 * lane;
            atomicAdd(ag + 0, o.x);
            atomicAdd(ag + 1, o.y);
            atomicAdd(ag + 2, o.z);
            atomicAdd(ag + 3, o.w);
        }
        __syncwarp();
    }
}

// ---------------------------------------------------------------------------
// Kernel 3: node processor. h1 = silu(Pn + agg@nw1b); h2; m; LN; x residual.
// ---------------------------------------------------------------------------
__global__ void __launch_bounds__(512, 1) node_kernel(
    const float* __restrict__ x,
    const float* __restrict__ nw1,    // [256,128] (use rows 128..255)
    const float* __restrict__ nw2,
    const float* __restrict__ nw3,
    const float* __restrict__ nb2,
    const float* __restrict__ nb3,
    const float* __restrict__ nlg,
    const float* __restrict__ nlb,
    float* __restrict__ outX)         // [N, 128]
{
    extern __shared__ float sm[];
    float* sW1 = sm;
    float* sW2 = sW1 + 16384;
    float* sW3 = sW2 + 16384;
    float* sB  = sW3 + 16384;
    float* sRows = sB + 512;

    for (int idx = threadIdx.x; idx < 16384; idx += 512) {
        sW1[idx] = nw1[16384 + idx];
        sW2[idx] = nw2[idx];
        sW3[idx] = nw3[idx];
    }
    if (threadIdx.x < 128) {
        int c = threadIdx.x;
        sB[c] = nb2[c]; sB[128 + c] = nb3[c]; sB[256 + c] = nlg[c]; sB[384 + c] = nlb[c];
    }
    __syncthreads();

    const int warp = threadIdx.x >> 5, lane = threadIdx.x & 31;
    const int gwarp  = blockIdx.x * 16 + warp;
    const int nwarps = gridDim.x * 16;
    float* myrow = sRows + warp * 512;

    float4 b2v = ((const float4*)sB)[lane];
    float4 b3v = ((const float4*)(sB + 128))[lane];
    float4 gv  = ((const float4*)(sB + 256))[lane];
    float4 bv  = ((const float4*)(sB + 384))[lane];

    for (int q = gwarp; q < NQ_NODE; q += nwarps) {
        const int n0 = q * 4;
        const float4* src = (const float4*)(g_agg + (size_t)n0 * DIM);
        float4* rows4 = (float4*)myrow;
        #pragma unroll
        for (int t = lane; t < 128; t += 32) rows4[t] = src[t];
        __syncwarp();

        float4 acc[4];
        #pragma unroll
        for (int t = 0; t < 4; t++)
            acc[t] = ((const float4*)(g_Pn + (size_t)(n0 + t) * DIM))[lane];

        layer128(sW1, myrow, lane, acc);              // + agg @ nw1b (bias in Pn)
        __syncwarp();
        #pragma unroll
        for (int t = 0; t < 4; t++) rows4[t * 32 + lane] = silu4(acc[t]);
        __syncwarp();

        #pragma unroll
        for (int t = 0; t < 4; t++) acc[t] = b2v;
        layer128(sW2, myrow, lane, acc);
        __syncwarp();
        #pragma unroll
        for (int t = 0; t < 4; t++) rows4[t * 32 + lane] = silu4(acc[t]);
        __syncwarp();

        #pragma unroll
        for (int t = 0; t < 4; t++) acc[t] = b3v;
        layer128(sW3, myrow, lane, acc);

        float s[4], ss[4];
        #pragma unroll
        for (int t = 0; t < 4; t++) {
            float4 m = acc[t];
            s[t]  = m.x + m.y + m.z + m.w;
            ss[t] = m.x * m.x + m.y * m.y + m.z * m.z + m.w * m.w;
        }
        ln_reduce(s, ss);
        #pragma unroll
        for (int t = 0; t < 4; t++) {
            float mean = s[t] * (1.0f / 128.0f);
            float var  = ss[t] * (1.0f / 128.0f) - mean * mean;
            float inv  = rsqrtf(var + EPS_LN);
            float4 xr = ((const float4*)(x + (size_t)(n0 + t) * DIM))[lane];
            float4 m = acc[t];
            float4 o;
            o.x = xr.x + (m.x - mean) * inv * gv.x + bv.x;
            o.y = xr.y + (m.y - mean) * inv * gv.y + bv.y;
            o.z = xr.z + (m.z - mean) * inv * gv.z + bv.z;
            o.w = xr.w + (m.w - mean) * inv * gv.w + bv.w;
            ((float4*)(outX + (size_t)(n0 + t) * DIM))[lane] = o;
        }
        __syncwarp();
    }
}

// ---------------------------------------------------------------------------
extern "C" void kernel_launch(void* const* d_in, const int* in_sizes, int n_in,
                              void* d_out, int out_size) {
    const float* x   = (const float*)d_in[0];
    const int*   ei  = (const int*)  d_in[1];
    const float* ea  = (const float*)d_in[2];
    const float* ew1 = (const float*)d_in[3];
    const float* eb1 = (const float*)d_in[4];
    const float* ew2 = (const float*)d_in[5];
    const float* eb2 = (const float*)d_in[6];
    const float* ew3 = (const float*)d_in[7];
    const float* eb3 = (const float*)d_in[8];
    const float* elg = (const float*)d_in[9];
    const float* elb = (const float*)d_in[10];
    const float* nw1 = (const float*)d_in[11];
    const float* nb1 = (const float*)d_in[12];
    const float* nw2 = (const float*)d_in[13];
    const float* nb2 = (const float*)d_in[14];
    const float* nw3 = (const float*)d_in[15];
    const float* nb3 = (const float*)d_in[16];
    const float* nlg = (const float*)d_in[17];
    const float* nlb = (const float*)d_in[18];

    float* outX = (float*)d_out;
    float* outE = outX + (size_t)NNODE * DIM;

    const size_t smem_pre  = (size_t)(3 * 16384 + 256 + 16 * 512) * 4;  // 230400
    const size_t smem_main = (size_t)(3 * 16384 + 512 + 16 * 512) * 4;  // 231424
    cudaFuncSetAttribute(precompute_kernel, cudaFuncAttributeMaxDynamicSharedMemorySize, (int)smem_pre);
    cudaFuncSetAttribute(edge_kernel,       cudaFuncAttributeMaxDynamicSharedMemorySize, (int)smem_main);
    cudaFuncSetAttribute(node_kernel,       cudaFuncAttributeMaxDynamicSharedMemorySize, (int)smem_main);

    void* aggp = nullptr;
    cudaGetSymbolAddress(&aggp, g_agg);
    cudaMemsetAsync(aggp, 0, sizeof(float) * (size_t)NNODE * DIM, 0);

    precompute_kernel<<<152, 512, smem_pre>>>(x, ew1, eb1, nw1, nb1);
    edge_kernel<<<152, 512, smem_main>>>(ei, ea, ew1, ew2, ew3, eb2, eb3, elg, elb, outE);
    node_kernel<<<152, 512, smem_main>>>(x, nw1, nw2, nw3, nb2, nb3, nlg, nlb, outX);
}

// round 2
// speedup vs baseline: 1.0592x; 1.0592x over previous
#include <cuda_runtime.h>

#define NNODE 50000
#define NEDGE 800000
#define DIM   128
#define NQ_NODE (NNODE/4)   // 12500
#define NQ_EDGE (NEDGE/4)   // 200000
#define EPS_LN 1e-5f

// Scratch (device globals: no allocations allowed)
__device__ float g_Pa[NNODE*DIM];   // x @ ew1[0:128]   + eb1
__device__ float g_Pb[NNODE*DIM];   // x @ ew1[128:256]
__device__ float g_Pn[NNODE*DIM];   // x @ nw1[0:128]   + nb1
__device__ float g_agg[NNODE*DIM];  // segment_sum(edge_attr_new, j)

__device__ __forceinline__ float silu_f(float v) {
    return v * (1.0f / (1.0f + __expf(-v)));
}
__device__ __forceinline__ float4 silu4(float4 v) {
    return make_float4(silu_f(v.x), silu_f(v.y), silu_f(v.z), silu_f(v.w));
}

// One 128->128 dense layer step for 4 rows held in smem (myrow: 4 x 128 floats).
// Lane owns output cols [4*lane, 4*lane+4). acc must be pre-initialized (bias).
__device__ __forceinline__ void layer128(const float* __restrict__ sW,
                                         const float* __restrict__ myrow,
                                         int lane, float4 acc[4]) {
    #pragma unroll 4
    for (int k = 0; k < 128; k++) {
        float4 w = ((const float4*)sW)[k * 32 + lane];
        float e0 = myrow[k];
        float e1 = myrow[128 + k];
        float e2 = myrow[256 + k];
        float e3 = myrow[384 + k];
        acc[0].x = fmaf(e0, w.x, acc[0].x); acc[0].y = fmaf(e0, w.y, acc[0].y);
        acc[0].z = fmaf(e0, w.z, acc[0].z); acc[0].w = fmaf(e0, w.w, acc[0].w);
        acc[1].x = fmaf(e1, w.x, acc[1].x); acc[1].y = fmaf(e1, w.y, acc[1].y);
        acc[1].z = fmaf(e1, w.z, acc[1].z); acc[1].w = fmaf(e1, w.w, acc[1].w);
        acc[2].x = fmaf(e2, w.x, acc[2].x); acc[2].y = fmaf(e2, w.y, acc[2].y);
        acc[2].z = fmaf(e2, w.z, acc[2].z); acc[2].w = fmaf(e2, w.w, acc[2].w);
        acc[3].x = fmaf(e3, w.x, acc[3].x); acc[3].y = fmaf(e3, w.y, acc[3].y);
        acc[3].z = fmaf(e3, w.z, acc[3].z); acc[3].w = fmaf(e3, w.w, acc[3].w);
    }
}

// Warp-wide allreduce of per-row sum / sumsq for 4 rows.
__device__ __forceinline__ void ln_reduce(float s[4], float ss[4]) {
    #pragma unroll
    for (int o = 16; o > 0; o >>= 1) {
        #pragma unroll
        for (int t = 0; t < 4; t++) {
            s[t]  += __shfl_xor_sync(0xffffffffu, s[t],  o);
            ss[t] += __shfl_xor_sync(0xffffffffu, ss[t], o);
        }
    }
}

// ---------------------------------------------------------------------------
// Kernel 1: per-node projections Pa = x@W1a + eb1, Pb = x@W1b, Pn = x@nw1a + nb1
// ---------------------------------------------------------------------------
__global__ void __launch_bounds__(512, 1) precompute_kernel(
    const float* __restrict__ x,
    const float* __restrict__ ew1, const float* __restrict__ eb1,
    const float* __restrict__ nw1, const float* __restrict__ nb1)
{
    extern __shared__ float sm[];
    float* sWa = sm;               // 16384
    float* sWb = sWa + 16384;      // 16384
    float* sWn = sWb + 16384;      // 16384
    float* sB  = sWn + 16384;      // 256: eb1 | nb1
    float* sRows = sB + 256;       // 16 warps * 512

    for (int idx = threadIdx.x; idx < 16384; idx += 512) {
        sWa[idx] = ew1[idx];               // rows 0..127
        sWb[idx] = ew1[16384 + idx];       // rows 128..255
        sWn[idx] = nw1[idx];               // rows 0..127
    }
    if (threadIdx.x < 128) {
        sB[threadIdx.x]       = eb1[threadIdx.x];
        sB[128 + threadIdx.x] = nb1[threadIdx.x];
    }
    __syncthreads();

    const int warp = threadIdx.x >> 5, lane = threadIdx.x & 31;
    const int gwarp  = blockIdx.x * 16 + warp;
    const int nwarps = gridDim.x * 16;
    float* myrow = sRows + warp * 512;

    float4 eb1v = ((const float4*)sB)[lane];
    float4 nb1v = ((const float4*)(sB + 128))[lane];

    for (int q = gwarp; q < NQ_NODE; q += nwarps) {
        const int n0 = q * 4;
        const float4* src = (const float4*)(x + (size_t)n0 * DIM);
        float4* rows4 = (float4*)myrow;
        #pragma unroll
        for (int t = lane; t < 128; t += 32) rows4[t] = src[t];
        __syncwarp();

        float4 aA[4], aB[4], aN[4];
        #pragma unroll
        for (int t = 0; t < 4; t++) {
            aA[t] = eb1v; aB[t] = make_float4(0.f, 0.f, 0.f, 0.f); aN[t] = nb1v;
        }
        #pragma unroll 2
        for (int k = 0; k < 128; k++) {
            float4 wa = ((const float4*)sWa)[k * 32 + lane];
            float4 wb = ((const float4*)sWb)[k * 32 + lane];
            float4 wn = ((const float4*)sWn)[k * 32 + lane];
            #pragma unroll
            for (int t = 0; t < 4; t++) {
                float e = myrow[t * 128 + k];
                aA[t].x = fmaf(e, wa.x, aA[t].x); aA[t].y = fmaf(e, wa.y, aA[t].y);
                aA[t].z = fmaf(e, wa.z, aA[t].z); aA[t].w = fmaf(e, wa.w, aA[t].w);
                aB[t].x = fmaf(e, wb.x, aB[t].x); aB[t].y = fmaf(e, wb.y, aB[t].y);
                aB[t].z = fmaf(e, wb.z, aB[t].z); aB[t].w = fmaf(e, wb.w, aB[t].w);
                aN[t].x = fmaf(e, wn.x, aN[t].x); aN[t].y = fmaf(e, wn.y, aN[t].y);
                aN[t].z = fmaf(e, wn.z, aN[t].z); aN[t].w = fmaf(e, wn.w, aN[t].w);
            }
        }
        #pragma unroll
        for (int t = 0; t < 4; t++) {
            ((float4*)(g_Pa + (size_t)(n0 + t) * DIM))[lane] = aA[t];
            ((float4*)(g_Pb + (size_t)(n0 + t) * DIM))[lane] = aB[t];
            ((float4*)(g_Pn + (size_t)(n0 + t) * DIM))[lane] = aN[t];
        }
        __syncwarp();
    }
}

// ---------------------------------------------------------------------------
// Kernel 2: edge processor. h1 = silu(Pa[i]+Pb[j]+ea@W1c); h2; m; LN; residual;
// writes edge_attr_new and scatter-adds it into g_agg[j].
// ---------------------------------------------------------------------------
__global__ void __launch_bounds__(512, 1) edge_kernel(
    const int*   __restrict__ ei,     // [2, E]
    const float* __restrict__ ea,     // [E, 128]
    const float* __restrict__ ew1,    // [384, 128] (use rows 256..383)
    const float* __restrict__ ew2,
    const float* __restrict__ ew3,
    const float* __restrict__ eb2,
    const float* __restrict__ eb3,
    const float* __restrict__ elg,
    const float* __restrict__ elb,
    float* __restrict__ outE)         // [E, 128]
{
    extern __shared__ float sm[];
    float* sW1 = sm;               // W1c
    float* sW2 = sW1 + 16384;
    float* sW3 = sW2 + 16384;
    float* sB  = sW3 + 16384;      // eb2 | eb3 | gamma | beta
    float* sRows = sB + 512;

    for (int idx = threadIdx.x; idx < 16384; idx += 512) {
        sW1[idx] = ew1[32768 + idx];
        sW2[idx] = ew2[idx];
        sW3[idx] = ew3[idx];
    }
    if (threadIdx.x < 128) {
        int c = threadIdx.x;
        sB[c] = eb2[c]; sB[128 + c] = eb3[c]; sB[256 + c] = elg[c]; sB[384 + c] = elb[c];
    }
    __syncthreads();

    const int warp = threadIdx.x >> 5, lane = threadIdx.x & 31;
    const int gwarp  = blockIdx.x * 16 + warp;
    const int nwarps = gridDim.x * 16;
    float* myrow = sRows + warp * 512;

    float4 b2v = ((const float4*)sB)[lane];
    float4 b3v = ((const float4*)(sB + 128))[lane];
    float4 gv  = ((const float4*)(sB + 256))[lane];
    float4 bv  = ((const float4*)(sB + 384))[lane];

    for (int q = gwarp; q < NQ_EDGE; q += nwarps) {
        const int e0 = q * 4;
        int iq[4], jq[4];
        #pragma unroll
        for (int t = 0; t < 4; t++) {
            iq[t] = ei[e0 + t];
            jq[t] = ei[NEDGE + e0 + t];
        }
        // stage 4 contiguous edge_attr rows into smem
        const float4* src = (const float4*)(ea + (size_t)e0 * DIM);
        float4* rows4 = (float4*)myrow;
        #pragma unroll
        for (int t = lane; t < 128; t += 32) rows4[t] = src[t];
        __syncwarp();

        float4 resid[4];
        float4 acc[4];
        #pragma unroll
        for (int t = 0; t < 4; t++) {
            resid[t] = rows4[t * 32 + lane];
            float4 pa = ((const float4*)(g_Pa + (size_t)iq[t] * DIM))[lane];
            float4 pb = ((const float4*)(g_Pb + (size_t)jq[t] * DIM))[lane];
            acc[t] = make_float4(pa.x + pb.x, pa.y + pb.y, pa.z + pb.z, pa.w + pb.w);
        }

        layer128(sW1, myrow, lane, acc);              // + ea @ W1c (bias in Pa)
        __syncwarp();
        #pragma unroll
        for (int t = 0; t < 4; t++) rows4[t * 32 + lane] = silu4(acc[t]);
        __syncwarp();

        #pragma unroll
        for (int t = 0; t < 4; t++) acc[t] = b2v;
        layer128(sW2, myrow, lane, acc);
        __syncwarp();
        #pragma unroll
        for (int t = 0; t < 4; t++) rows4[t * 32 + lane] = silu4(acc[t]);
        __syncwarp();

        #pragma unroll
        for (int t = 0; t < 4; t++) acc[t] = b3v;
        layer128(sW3, myrow, lane, acc);

        // LayerNorm per row + residual + scatter
        float s[4], ss[4];
        #pragma unroll
        for (int t = 0; t < 4; t++) {
            float4 m = acc[t];
            s[t]  = m.x + m.y + m.z + m.w;
            ss[t] = m.x * m.x + m.y * m.y + m.z * m.z + m.w * m.w;
        }
        ln_reduce(s, ss);
        #pragma unroll
        for (int t = 0; t < 4; t++) {
            float mean = s[t] * (1.0f / 128.0f);
            float var  = ss[t] * (1.0f / 128.0f) - mean * mean;
            float inv  = rsqrtf(var + EPS_LN);
            float4 m = acc[t];
            float4 o;
            o.x = resid[t].x + (m.x - mean) * inv * gv.x + bv.x;
            o.y = resid[t].y + (m.y - mean) * inv * gv.y + bv.y;
            o.z = resid[t].z + (m.z - mean) * inv * gv.z + bv.z;
            o.w = resid[t].w + (m.w - mean) * inv * gv.w + bv.w;
            ((float4*)(outE + (size_t)(e0 + t) * DIM))[lane] = o;
            float* ag = g_agg + (size_t)jq[t] * DIM + 4 * lane;
            atomicAdd(ag + 0, o.x);
            atomicAdd(ag + 1, o.y);
            atomicAdd(ag + 2, o.z);
            atomicAdd(ag + 3, o.w);
        }
        __syncwarp();
    }
}

// ---------------------------------------------------------------------------
// Kernel 3: node processor. h1 = silu(Pn + agg@nw1b); h2; m; LN; x residual.
// ---------------------------------------------------------------------------
__global__ void __launch_bounds__(512, 1) node_kernel(
    const float* __restrict__ x,
    const float* __restrict__ nw1,    // [256,128] (use rows 128..255)
    const float* __restrict__ nw2,
    const float* __restrict__ nw3,
    const float* __restrict__ nb2,
    const float* __restrict__ nb3,
    const float* __restrict__ nlg,
    const float* __restrict__ nlb,
    float* __restrict__ outX)         // [N, 128]
{
    extern __shared__ float sm[];
    float* sW1 = sm;
    float* sW2 = sW1 + 16384;
    float* sW3 = sW2 + 16384;
    float* sB  = sW3 + 16384;
    float* sRows = sB + 512;

    for (int idx = threadIdx.x; idx < 16384; idx += 512) {
        sW1[idx] = nw1[16384 + idx];
        sW2[idx] = nw2[idx];
        sW3[idx] = nw3[idx];
    }
    if (threadIdx.x < 128) {
        int c = threadIdx.x;
        sB[c] = nb2[c]; sB[128 + c] = nb3[c]; sB[256 + c] = nlg[c]; sB[384 + c] = nlb[c];
    }
    __syncthreads();

    const int warp = threadIdx.x >> 5, lane = threadIdx.x & 31;
    const int gwarp  = blockIdx.x * 16 + warp;
    const int nwarps = gridDim.x * 16;
    float* myrow = sRows + warp * 512;

    float4 b2v = ((const float4*)sB)[lane];
    float4 b3v = ((const float4*)(sB + 128))[lane];
    float4 gv  = ((const float4*)(sB + 256))[lane];
    float4 bv  = ((const float4*)(sB + 384))[lane];

    for (int q = gwarp; q < NQ_NODE; q += nwarps) {
        const int n0 = q * 4;
        const float4* src = (const float4*)(g_agg + (size_t)n0 * DIM);
        float4* rows4 = (float4*)myrow;
        #pragma unroll
        for (int t = lane; t < 128; t += 32) rows4[t] = src[t];
        __syncwarp();

        float4 acc[4];
        #pragma unroll
        for (int t = 0; t < 4; t++)
            acc[t] = ((const float4*)(g_Pn + (size_t)(n0 + t) * DIM))[lane];

        layer128(sW1, myrow, lane, acc);              // + agg @ nw1b (bias in Pn)
        __syncwarp();
        #pragma unroll
        for (int t = 0; t < 4; t++) rows4[t * 32 + lane] = silu4(acc[t]);
        __syncwarp();

        #pragma unroll
        for (int t = 0; t < 4; t++) acc[t] = b2v;
        layer128(sW2, myrow, lane, acc);
        __syncwarp();
        #pragma unroll
        for (int t = 0; t < 4; t++) rows4[t * 32 + lane] = silu4(acc[t]);
        __syncwarp();

        #pragma unroll
        for (int t = 0; t < 4; t++) acc[t] = b3v;
        layer128(sW3, myrow, lane, acc);

        float s[4], ss[4];
        #pragma unroll
        for (int t = 0; t < 4; t++) {
            float4 m = acc[t];
            s[t]  = m.x + m.y + m.z + m.w;
            ss[t] = m.x * m.x + m.y * m.y + m.z * m.z + m.w * m.w;
        }
        ln_reduce(s, ss);
        #pragma unroll
        for (int t = 0; t < 4; t++) {
            float mean = s[t] * (1.0f / 128.0f);
            float var  = ss[t] * (1.0f / 128.0f) - mean * mean;
            float inv  = rsqrtf(var + EPS_LN);
            float4 xr = ((const float4*)(x + (size_t)(n0 + t) * DIM))[lane];
            float4 m = acc[t];
            float4 o;
            o.x = xr.x + (m.x - mean) * inv * gv.x + bv.x;
            o.y = xr.y + (m.y - mean) * inv * gv.y + bv.y;
            o.z = xr.z + (m.z - mean) * inv * gv.z + bv.z;
            o.w = xr.w + (m.w - mean) * inv * gv.w + bv.w;
            ((float4*)(outX + (size_t)(n0 + t) * DIM))[lane] = o;
        }
        __syncwarp();
    }
}

// ---------------------------------------------------------------------------
extern "C" void kernel_launch(void* const* d_in, const int* in_sizes, int n_in,
                              void* d_out, int out_size) {
    const float* x   = (const float*)d_in[0];
    const int*   ei  = (const int*)  d_in[1];
    const float* ea  = (const float*)d_in[2];
    const float* ew1 = (const float*)d_in[3];
    const float* eb1 = (const float*)d_in[4];
    const float* ew2 = (const float*)d_in[5];
    const float* eb2 = (const float*)d_in[6];
    const float* ew3 = (const float*)d_in[7];
    const float* eb3 = (const float*)d_in[8];
    const float* elg = (const float*)d_in[9];
    const float* elb = (const float*)d_in[10];
    const float* nw1 = (const float*)d_in[11];
    const float* nb1 = (const float*)d_in[12];
    const float* nw2 = (const float*)d_in[13];
    const float* nb2 = (const float*)d_in[14];
    const float* nw3 = (const float*)d_in[15];
    const float* nb3 = (const float*)d_in[16];
    const float* nlg = (const float*)d_in[17];
    const float* nlb = (const float*)d_in[18];

    float* outX = (float*)d_out;
    float* outE = outX + (size_t)NNODE * DIM;

    const size_t smem_pre  = (size_t)(3 * 16384 + 256 + 16 * 512) * 4;  // 230400
    const size_t smem_main = (size_t)(3 * 16384 + 512 + 16 * 512) * 4;  // 231424
    cudaFuncSetAttribute(precompute_kernel, cudaFuncAttributeMaxDynamicSharedMemorySize, (int)smem_pre);
    cudaFuncSetAttribute(edge_kernel,       cudaFuncAttributeMaxDynamicSharedMemorySize, (int)smem_main);
    cudaFuncSetAttribute(node_kernel,       cudaFuncAttributeMaxDynamicSharedMemorySize, (int)smem_main);

    void* aggp = nullptr;
    cudaGetSymbolAddress(&aggp, g_agg);
    cudaMemsetAsync(aggp, 0, sizeof(float) * (size_t)NNODE * DIM, 0);

    precompute_kernel<<<152, 512, smem_pre>>>(x, ew1, eb1, nw1, nb1);
    edge_kernel<<<152, 512, smem_main>>>(ei, ea, ew1, ew2, ew3, eb2, eb3, elg, elb, outE);
    node_kernel<<<152, 512, smem_main>>>(x, nw1, nw2, nw3, nb2, nb3, nlg, nlb, outX);
}

// round 4
// speedup vs baseline: 1.7921x; 1.6919x over previous
#include <cuda_runtime.h>
#include <cstdint>

#define NNODE 50000
#define NEDGE 800000
#define EPS_LN 1e-5f
#define EDGE_TTILES 50000   // 800000/16
#define NODE_TTILES 3125    // 50000/16
#define ASTRIDE 132

__device__ __align__(16) float g_Pa[NNODE*128];
__device__ __align__(16) float g_Pb[NNODE*128];
__device__ __align__(16) float g_Pn[NNODE*128];
__device__ __align__(16) float g_agg[NNODE*128];

__device__ __forceinline__ uint32_t f2tf(float f){
    uint32_t u; asm("cvt.rna.tf32.f32 %0, %1;" : "=r"(u) : "f"(f)); return u;
}
__device__ __forceinline__ float sigl(float v){ return v * (1.0f/(1.0f + __expf(-v))); }

#define TBAR(id) asm volatile("bar.sync %0, 128;" :: "r"(id) : "memory")

__device__ __forceinline__ void mma8(float* d, const uint32_t* a, uint32_t b0, uint32_t b1){
    asm volatile("mma.sync.aligned.m16n8k8.row.col.f32.tf32.tf32.f32 "
        "{%0,%1,%2,%3}, {%4,%5,%6,%7}, {%8,%9}, {%0,%1,%2,%3};"
        : "+f"(d[0]), "+f"(d[1]), "+f"(d[2]), "+f"(d[3])
        : "r"(a[0]), "r"(a[1]), "r"(a[2]), "r"(a[3]), "r"(b0), "r"(b1));
}

// W[k][n] row-major [128,128] -> SMEM fragment order, tf32-rounded.
// float4 at ((ntile*8+kpair)*32 + lane) = {b0(ks even), b1(ks even), b0(ks odd), b1(ks odd)}
__device__ void load_wfrag(const float* __restrict__ W, float* __restrict__ dst,
                           int tid, int nthr){
    for (int idx = tid; idx < 16384; idx += nthr){
        int q = idx & 3, lane = (idx >> 2) & 31, kpair = (idx >> 7) & 7, ntile = idx >> 10;
        int tig = lane & 3, g = lane >> 2;
        int kstep = kpair * 2 + (q >> 1);
        int k = kstep * 8 + tig + (q & 1) * 4;
        int n = ntile * 8 + g;
        dst[idx] = __uint_as_float(f2tf(W[k * 128 + n]));
    }
}

// acc[nt][0..3] = (16x128 A in SMEM) x (128x128 W frag in SMEM), warp owns cols wt*32..+31
__device__ __forceinline__ void gemm_layer(const float* __restrict__ Ab,
                                           const float* __restrict__ sWf,
                                           int wt, int lane, float acc[4][4]){
    const int g = lane >> 2, tig = lane & 3;
    #pragma unroll
    for (int nt = 0; nt < 4; nt++)
        #pragma unroll
        for (int j = 0; j < 4; j++) acc[nt][j] = 0.f;
    #pragma unroll
    for (int kp = 0; kp < 8; kp++){
        const int k0 = kp * 16;
        uint32_t af0[4], af1[4];
        af0[0] = __float_as_uint(Ab[ g     *ASTRIDE + k0 + tig    ]);
        af0[1] = __float_as_uint(Ab[(g+8)  *ASTRIDE + k0 + tig    ]);
        af0[2] = __float_as_uint(Ab[ g     *ASTRIDE + k0 + tig + 4]);
        af0[3] = __float_as_uint(Ab[(g+8)  *ASTRIDE + k0 + tig + 4]);
        af1[0] = __float_as_uint(Ab[ g     *ASTRIDE + k0 + 8 + tig    ]);
        af1[1] = __float_as_uint(Ab[(g+8)  *ASTRIDE + k0 + 8 + tig    ]);
        af1[2] = __float_as_uint(Ab[ g     *ASTRIDE + k0 + 8 + tig + 4]);
        af1[3] = __float_as_uint(Ab[(g+8)  *ASTRIDE + k0 + 8 + tig + 4]);
        #pragma unroll
        for (int nt = 0; nt < 4; nt++){
            float4 w = ((const float4*)sWf)[((wt*4 + nt)*8 + kp)*32 + lane];
            mma8(acc[nt], af0, __float_as_uint(w.x), __float_as_uint(w.y));
            mma8(acc[nt], af1, __float_as_uint(w.z), __float_as_uint(w.w));
        }
    }
}

// stage 16 contiguous rows (128 floats each) into team A buffer (stride 132)
__device__ __forceinline__ void stage16(const float* __restrict__ src, float* __restrict__ Ab,
                                        int tt){
    const float4* s4 = (const float4*)src;
    #pragma unroll
    for (int rep = 0; rep < 4; rep++){
        int idx = tt + rep * 128;
        int row = idx >> 5, c4 = idx & 31;
        float4 v = s4[idx];
        *(float4*)(Ab + row * ASTRIDE + c4 * 4) = v;
    }
}

// ------------------------------------------------------------------ kernel 1
// Pa = x@W1a + eb1 ; Pb = x@W1b ; Pn = x@nW1a + nb1
__global__ void __launch_bounds__(256, 1) pre_kernel(
    const float* __restrict__ x,
    const float* __restrict__ ew1, const float* __restrict__ eb1,
    const float* __restrict__ nw1, const float* __restrict__ nb1)
{
    extern __shared__ float sm[];
    float* sW0 = sm;            // W1a frag
    float* sW1 = sm + 16384;    // W1b frag
    float* sW2 = sm + 32768;    // nW1a frag
    float* sB  = sm + 49152;    // eb1 | nb1
    float* sA  = sm + 49408;    // 2 teams * 16*132

    const int tid = threadIdx.x;
    load_wfrag(ew1,         sW0, tid, 256);
    load_wfrag(ew1 + 16384, sW1, tid, 256);
    load_wfrag(nw1,         sW2, tid, 256);
    if (tid < 128){ sB[tid] = eb1[tid]; sB[128 + tid] = nb1[tid]; }
    __syncthreads();

    const int wid = tid >> 5, lane = tid & 31, team = wid >> 2, wt = wid & 3;
    const int g = lane >> 2, tig = lane & 3, tt = tid & 127, bid = 1 + team;
    float* Ab = sA + team * (16 * ASTRIDE);

    for (int tile = blockIdx.x * 2 + team; tile < NODE_TTILES; tile += gridDim.x * 2){
        const int n0 = tile * 16;
        TBAR(bid);
        stage16(x + (size_t)n0 * 128, Ab, tt);
        TBAR(bid);
        const int rA = n0 + g, rB = n0 + g + 8;

        float acc[4][4];
        #pragma unroll
        for (int L = 0; L < 3; L++){
            gemm_layer(Ab, (L==0)?sW0:((L==1)?sW1:sW2), wt, lane, acc);
            float* dst = (L==0) ? g_Pa : ((L==1) ? g_Pb : g_Pn);
            const float* bias = (L==0) ? sB : ((L==2) ? sB + 128 : nullptr);
            #pragma unroll
            for (int nt = 0; nt < 4; nt++){
                int col = wt*32 + nt*8 + tig*2;
                float b0 = bias ? bias[col] : 0.f, b1 = bias ? bias[col+1] : 0.f;
                float2 oA = { acc[nt][0] + b0, acc[nt][1] + b1 };
                float2 oB = { acc[nt][2] + b0, acc[nt][3] + b1 };
                *(float2*)(dst + (size_t)rA * 128 + col) = oA;
                *(float2*)(dst + (size_t)rB * 128 + col) = oB;
            }
        }
    }
}

// ------------------------------------------------------------------ kernel 2
__global__ void __launch_bounds__(256, 1) edge_kernel(
    const int* __restrict__ ei, const float* __restrict__ ea,
    const float* __restrict__ ew1, const float* __restrict__ ew2, const float* __restrict__ ew3,
    const float* __restrict__ eb2, const float* __restrict__ eb3,
    const float* __restrict__ elg, const float* __restrict__ elb,
    float* __restrict__ outE)
{
    extern __shared__ float sm[];
    float* sW1 = sm;            // W1c frag
    float* sW2 = sm + 16384;
    float* sW3 = sm + 32768;
    float* sB  = sm + 49152;    // eb2 | eb3 | gamma | beta
    float* sRed= sm + 49664;    // [256]: sum[128] | ssq[128]
    float* sA  = sm + 49920;

    const int tid = threadIdx.x;
    load_wfrag(ew1 + 32768, sW1, tid, 256);
    load_wfrag(ew2,         sW2, tid, 256);
    load_wfrag(ew3,         sW3, tid, 256);
    if (tid < 128){
        sB[tid] = eb2[tid]; sB[128+tid] = eb3[tid]; sB[256+tid] = elg[tid]; sB[384+tid] = elb[tid];
    }
    __syncthreads();

    const int wid = tid >> 5, lane = tid & 31, team = wid >> 2, wt = wid & 3;
    const int g = lane >> 2, tig = lane & 3, tt = tid & 127, bid = 1 + team;
    float* Ab = sA + team * (16 * ASTRIDE);

    for (int tile = blockIdx.x * 2 + team; tile < EDGE_TTILES; tile += gridDim.x * 2){
        const int e0 = tile * 16;
        TBAR(bid);
        stage16(ea + (size_t)e0 * 128, Ab, tt);
        TBAR(bid);

        const int eA = e0 + g, eB = e0 + g + 8;
        const int viA = ei[eA], vjA = ei[NEDGE + eA];
        const int viB = ei[eB], vjB = ei[NEDGE + eB];

        float acc[4][4];
        // ---- layer 1: ea @ W1c, + Pa[i] + Pb[j], silu
        gemm_layer(Ab, sW1, wt, lane, acc);
        TBAR(bid);
        #pragma unroll
        for (int nt = 0; nt < 4; nt++){
            int col = wt*32 + nt*8 + tig*2;
            float2 paA = *(const float2*)(g_Pa + (size_t)viA*128 + col);
            float2 pbA = *(const float2*)(g_Pb + (size_t)vjA*128 + col);
            float2 paB = *(const float2*)(g_Pa + (size_t)viB*128 + col);
            float2 pbB = *(const float2*)(g_Pb + (size_t)vjB*128 + col);
            float2 wA = { __uint_as_float(f2tf(sigl(acc[nt][0] + paA.x + pbA.x))),
                          __uint_as_float(f2tf(sigl(acc[nt][1] + paA.y + pbA.y))) };
            float2 wB = { __uint_as_float(f2tf(sigl(acc[nt][2] + paB.x + pbB.x))),
                          __uint_as_float(f2tf(sigl(acc[nt][3] + paB.y + pbB.y))) };
            *(float2*)(Ab +  g   *ASTRIDE + col) = wA;
            *(float2*)(Ab + (g+8)*ASTRIDE + col) = wB;
        }
        TBAR(bid);
        // ---- layer 2: + eb2, silu
        gemm_layer(Ab, sW2, wt, lane, acc);
        TBAR(bid);
        #pragma unroll
        for (int nt = 0; nt < 4; nt++){
            int col = wt*32 + nt*8 + tig*2;
            float b0 = sB[col], b1 = sB[col+1];
            float2 wA = { __uint_as_float(f2tf(sigl(acc[nt][0] + b0))),
                          __uint_as_float(f2tf(sigl(acc[nt][1] + b1))) };
            float2 wB = { __uint_as_float(f2tf(sigl(acc[nt][2] + b0))),
                          __uint_as_float(f2tf(sigl(acc[nt][3] + b1))) };
            *(float2*)(Ab +  g   *ASTRIDE + col) = wA;
            *(float2*)(Ab + (g+8)*ASTRIDE + col) = wB;
        }
        TBAR(bid);
        // ---- layer 3: + eb3, LN, residual, scatter
        gemm_layer(Ab, sW3, wt, lane, acc);
        float s0=0.f,q0=0.f,s1=0.f,q1=0.f;
        #pragma unroll
        for (int nt = 0; nt < 4; nt++){
            int col = wt*32 + nt*8 + tig*2;
            acc[nt][0] += sB[128+col]; acc[nt][1] += sB[128+col+1];
            acc[nt][2] += sB[128+col]; acc[nt][3] += sB[128+col+1];
            s0 += acc[nt][0]+acc[nt][1]; q0 += acc[nt][0]*acc[nt][0]+acc[nt][1]*acc[nt][1];
            s1 += acc[nt][2]+acc[nt][3]; q1 += acc[nt][2]*acc[nt][2]+acc[nt][3]*acc[nt][3];
        }
        #pragma unroll
        for (int o = 1; o < 4; o <<= 1){
            s0 += __shfl_xor_sync(0xffffffffu, s0, o);
            q0 += __shfl_xor_sync(0xffffffffu, q0, o);
            s1 += __shfl_xor_sync(0xffffffffu, s1, o);
            q1 += __shfl_xor_sync(0xffffffffu, q1, o);
        }
        if (tig == 0){
            int ib = team*64 + wt*16;
            sRed[ib+g] = s0; sRed[ib+g+8] = s1;
            sRed[128+ib+g] = q0; sRed[128+ib+g+8] = q1;
        }
        TBAR(bid);
        float sumA=0.f,sqA=0.f,sumB=0.f,sqB=0.f;
        #pragma unroll
        for (int w2 = 0; w2 < 4; w2++){
            int ib = team*64 + w2*16;
            sumA += sRed[ib+g];   sqA += sRed[128+ib+g];
            sumB += sRed[ib+g+8]; sqB += sRed[128+ib+g+8];
        }
        float mA = sumA*(1.f/128.f), iA = rsqrtf(sqA*(1.f/128.f) - mA*mA + EPS_LN);
        float mB = sumB*(1.f/128.f), iB = rsqrtf(sqB*(1.f/128.f) - mB*mB + EPS_LN);
        #pragma unroll
        for (int nt = 0; nt < 4; nt++){
            int col = wt*32 + nt*8 + tig*2;
            float gm0 = sB[256+col], gm1 = sB[256+col+1];
            float bt0 = sB[384+col], bt1 = sB[384+col+1];
            float2 rA = *(const float2*)(ea + (size_t)eA*128 + col);
            float2 rB = *(const float2*)(ea + (size_t)eB*128 + col);
            float2 oA = { rA.x + (acc[nt][0]-mA)*iA*gm0 + bt0,
                          rA.y + (acc[nt][1]-mA)*iA*gm1 + bt1 };
            float2 oB = { rB.x + (acc[nt][2]-mB)*iB*gm0 + bt0,
                          rB.y + (acc[nt][3]-mB)*iB*gm1 + bt1 };
            *(float2*)(outE + (size_t)eA*128 + col) = oA;
            *(float2*)(outE + (size_t)eB*128 + col) = oB;
            asm volatile("red.global.add.v2.f32 [%0], {%1,%2};"
                         :: "l"(g_agg + (size_t)vjA*128 + col), "f"(oA.x), "f"(oA.y) : "memory");
            asm volatile("red.global.add.v2.f32 [%0], {%1,%2};"
                         :: "l"(g_agg + (size_t)vjB*128 + col), "f"(oB.x), "f"(oB.y) : "memory");
        }
    }
}

// ------------------------------------------------------------------ kernel 3
__global__ void __launch_bounds__(256, 1) node_kernel(
    const float* __restrict__ x,
    const float* __restrict__ nw1, const float* __restrict__ nw2, const float* __restrict__ nw3,
    const float* __restrict__ nb2, const float* __restrict__ nb3,
    const float* __restrict__ nlg, const float* __restrict__ nlb,
    float* __restrict__ outX)
{
    extern __shared__ float sm[];
    float* sW1 = sm;            // nW1b frag
    float* sW2 = sm + 16384;
    float* sW3 = sm + 32768;
    float* sB  = sm + 49152;
    float* sRed= sm + 49664;
    float* sA  = sm + 49920;

    const int tid = threadIdx.x;
    load_wfrag(nw1 + 16384, sW1, tid, 256);
    load_wfrag(nw2,         sW2, tid, 256);
    load_wfrag(nw3,         sW3, tid, 256);
    if (tid < 128){
        sB[tid] = nb2[tid]; sB[128+tid] = nb3[tid]; sB[256+tid] = nlg[tid]; sB[384+tid] = nlb[tid];
    }
    __syncthreads();

    const int wid = tid >> 5, lane = tid & 31, team = wid >> 2, wt = wid & 3;
    const int g = lane >> 2, tig = lane & 3, tt = tid & 127, bid = 1 + team;
    float* Ab = sA + team * (16 * ASTRIDE);

    for (int tile = blockIdx.x * 2 + team; tile < NODE_TTILES; tile += gridDim.x * 2){
        const int n0 = tile * 16;
        TBAR(bid);
        stage16(g_agg + (size_t)n0 * 128, Ab, tt);
        TBAR(bid);
        const int rA = n0 + g, rB = n0 + g + 8;

        float acc[4][4];
        // ---- layer 1: agg @ nW1b + Pn[row] (holds x@nW1a + nb1), silu
        gemm_layer(Ab, sW1, wt, lane, acc);
        TBAR(bid);
        #pragma unroll
        for (int nt = 0; nt < 4; nt++){
            int col = wt*32 + nt*8 + tig*2;
            float2 pnA = *(const float2*)(g_Pn + (size_t)rA*128 + col);
            float2 pnB = *(const float2*)(g_Pn + (size_t)rB*128 + col);
            float2 wA = { __uint_as_float(f2tf(sigl(acc[nt][0] + pnA.x))),
                          __uint_as_float(f2tf(sigl(acc[nt][1] + pnA.y))) };
            float2 wB = { __uint_as_float(f2tf(sigl(acc[nt][2] + pnB.x))),
                          __uint_as_float(f2tf(sigl(acc[nt][3] + pnB.y))) };
            *(float2*)(Ab +  g   *ASTRIDE + col) = wA;
            *(float2*)(Ab + (g+8)*ASTRIDE + col) = wB;
        }
        TBAR(bid);
        gemm_layer(Ab, sW2, wt, lane, acc);
        TBAR(bid);
        #pragma unroll
        for (int nt = 0; nt < 4; nt++){
            int col = wt*32 + nt*8 + tig*2;
            float b0 = sB[col], b1 = sB[col+1];
            float2 wA = { __uint_as_float(f2tf(sigl(acc[nt][0] + b0))),
                          __uint_as_float(f2tf(sigl(acc[nt][1] + b1))) };
            float2 wB = { __uint_as_float(f2tf(sigl(acc[nt][2] + b0))),
                          __uint_as_float(f2tf(sigl(acc[nt][3] + b1))) };
            *(float2*)(Ab +  g   *ASTRIDE + col) = wA;
            *(float2*)(Ab + (g+8)*ASTRIDE + col) = wB;
        }
        TBAR(bid);
        gemm_layer(Ab, sW3, wt, lane, acc);
        float s0=0.f,q0=0.f,s1=0.f,q1=0.f;
        #pragma unroll
        for (int nt = 0; nt < 4; nt++){
            int col = wt*32 + nt*8 + tig*2;
            acc[nt][0] += sB[128+col]; acc[nt][1] += sB[128+col+1];
            acc[nt][2] += sB[128+col]; acc[nt][3] += sB[128+col+1];
            s0 += acc[nt][0]+acc[nt][1]; q0 += acc[nt][0]*acc[nt][0]+acc[nt][1]*acc[nt][1];
            s1 += acc[nt][2]+acc[nt][3]; q1 += acc[nt][2]*acc[nt][2]+acc[nt][3]*acc[nt][3];
        }
        #pragma unroll
        for (int o = 1; o < 4; o <<= 1){
            s0 += __shfl_xor_sync(0xffffffffu, s0, o);
            q0 += __shfl_xor_sync(0xffffffffu, q0, o);
            s1 += __shfl_xor_sync(0xffffffffu, s1, o);
            q1 += __shfl_xor_sync(0xffffffffu, q1, o);
        }
        if (tig == 0){
            int ib = team*64 + wt*16;
            sRed[ib+g] = s0; sRed[ib+g+8] = s1;
            sRed[128+ib+g] = q0; sRed[128+ib+g+8] = q1;
        }
        TBAR(bid);
        float sumA=0.f,sqA=0.f,sumB=0.f,sqB=0.f;
        #pragma unroll
        for (int w2 = 0; w2 < 4; w2++){
            int ib = team*64 + w2*16;
            sumA += sRed[ib+g];   sqA += sRed[128+ib+g];
            sumB += sRed[ib+g+8]; sqB += sRed[128+ib+g+8];
        }
        float mA = sumA*(1.f/128.f), iA = rsqrtf(sqA*(1.f/128.f) - mA*mA + EPS_LN);
        float mB = sumB*(1.f/128.f), iB = rsqrtf(sqB*(1.f/128.f) - mB*mB + EPS_LN);
        #pragma unroll
        for (int nt = 0; nt < 4; nt++){
            int col = wt*32 + nt*8 + tig*2;
            float gm0 = sB[256+col], gm1 = sB[256+col+1];
            float bt0 = sB[384+col], bt1 = sB[384+col+1];
            float2 rxA = *(const float2*)(x + (size_t)rA*128 + col);
            float2 rxB = *(const float2*)(x + (size_t)rB*128 + col);
            float2 oA = { rxA.x + (acc[nt][0]-mA)*iA*gm0 + bt0,
                          rxA.y + (acc[nt][1]-mA)*iA*gm1 + bt1 };
            float2 oB = { rxB.x + (acc[nt][2]-mB)*iB*gm0 + bt0,
                          rxB.y + (acc[nt][3]-mB)*iB*gm1 + bt1 };
            *(float2*)(outX + (size_t)rA*128 + col) = oA;
            *(float2*)(outX + (size_t)rB*128 + col) = oB;
        }
    }
}

// ------------------------------------------------------------------ host
extern "C" void kernel_launch(void* const* d_in, const int* in_sizes, int n_in,
                              void* d_out, int out_size) {
    const float* x   = (const float*)d_in[0];
    const int*   ei  = (const int*)  d_in[1];
    const float* ea  = (const float*)d_in[2];
    const float* ew1 = (const float*)d_in[3];
    const float* eb1 = (const float*)d_in[4];
    const float* ew2 = (const float*)d_in[5];
    const float* eb2 = (const float*)d_in[6];
    const float* ew3 = (const float*)d_in[7];
    const float* eb3 = (const float*)d_in[8];
    const float* elg = (const float*)d_in[9];
    const float* elb = (const float*)d_in[10];
    const float* nw1 = (const float*)d_in[11];
    const float* nb1 = (const float*)d_in[12];
    const float* nw2 = (const float*)d_in[13];
    const float* nb2 = (const float*)d_in[14];
    const float* nw3 = (const float*)d_in[15];
    const float* nb3 = (const float*)d_in[16];
    const float* nlg = (const float*)d_in[17];
    const float* nlb = (const float*)d_in[18];

    float* outX = (float*)d_out;
    float* outE = outX + (size_t)NNODE * 128;

    // floats: pre = 49152+256+4224 = 53632 ; edge/node = 49152+512+256+4224 = 54144
    const size_t smem_pre  = 53632u * 4u;   // 214528
    const size_t smem_main = 54144u * 4u;   // 216576
    cudaFuncSetAttribute(pre_kernel,  cudaFuncAttributeMaxDynamicSharedMemorySize, (int)smem_pre);
    cudaFuncSetAttribute(edge_kernel, cudaFuncAttributeMaxDynamicSharedMemorySize, (int)smem_main);
    cudaFuncSetAttribute(node_kernel, cudaFuncAttributeMaxDynamicSharedMemorySize, (int)smem_main);

    void* aggp = nullptr;
    cudaGetSymbolAddress(&aggp, g_agg);
    cudaMemsetAsync(aggp, 0, sizeof(float) * (size_t)NNODE * 128, 0);

    pre_kernel<<<152, 256, smem_pre>>>(x, ew1, eb1, nw1, nb1);
    edge_kernel<<<152, 256, smem_main>>>(ei, ea, ew1, ew2, ew3, eb2, eb3, elg, elb, outE);
    node_kernel<<<152, 256, smem_main>>>(x, nw1, nw2, nw3, nb2, nb3, nlg, nlb, outX);
}

// round 5
// speedup vs baseline: 2.2266x; 1.2425x over previous
#include <cuda_runtime.h>
#include <cstdint>

#define NNODE 50000
#define NEDGE 800000
#define EPS_LN 1e-5f
#define EDGE_TTILES 50000   // 800000/16
#define NODE_TTILES 3125    // 50000/16
#define ASTRIDE 132
#define NTHREADS 384
#define NTEAMS 3

__device__ __align__(16) float g_Pa[NNODE*128];
__device__ __align__(16) float g_Pb[NNODE*128];
__device__ __align__(16) float g_Pn[NNODE*128];
__device__ __align__(16) float g_agg[NNODE*128];

__device__ __forceinline__ uint32_t f2tf(float f){
    uint32_t u; asm("cvt.rna.tf32.f32 %0, %1;" : "=r"(u) : "f"(f)); return u;
}
__device__ __forceinline__ float sigl(float v){ return v * (1.0f/(1.0f + __expf(-v))); }

#define TBAR(id) asm volatile("bar.sync %0, 128;" :: "r"(id) : "memory")

__device__ __forceinline__ void mma8(float* d, const uint32_t* a, uint32_t b0, uint32_t b1){
    asm volatile("mma.sync.aligned.m16n8k8.row.col.f32.tf32.tf32.f32 "
        "{%0,%1,%2,%3}, {%4,%5,%6,%7}, {%8,%9}, {%0,%1,%2,%3};"
        : "+f"(d[0]), "+f"(d[1]), "+f"(d[2]), "+f"(d[3])
        : "r"(a[0]), "r"(a[1]), "r"(a[2]), "r"(a[3]), "r"(b0), "r"(b1));
}

// W[k][n] row-major [128,128] -> SMEM fragment order, tf32-rounded.
__device__ void load_wfrag(const float* __restrict__ W, float* __restrict__ dst,
                           int tid, int nthr){
    for (int idx = tid; idx < 16384; idx += nthr){
        int q = idx & 3, lane = (idx >> 2) & 31, kpair = (idx >> 7) & 7, ntile = idx >> 10;
        int tig = lane & 3, g = lane >> 2;
        int kstep = kpair * 2 + (q >> 1);
        int k = kstep * 8 + tig + (q & 1) * 4;
        int n = ntile * 8 + g;
        dst[idx] = __uint_as_float(f2tf(W[k * 128 + n]));
    }
}

// acc[nt][0..3] = (16x128 A in SMEM) x (128x128 W frag), warp owns cols wt*32..+31
__device__ __forceinline__ void gemm_layer(const float* __restrict__ Ab,
                                           const float* __restrict__ sWf,
                                           int wt, int lane, float acc[4][4]){
    const int g = lane >> 2, tig = lane & 3;
    #pragma unroll
    for (int nt = 0; nt < 4; nt++)
        #pragma unroll
        for (int j = 0; j < 4; j++) acc[nt][j] = 0.f;
    #pragma unroll
    for (int kp = 0; kp < 8; kp++){
        const int k0 = kp * 16;
        uint32_t af0[4], af1[4];
        af0[0] = __float_as_uint(Ab[ g     *ASTRIDE + k0 + tig    ]);
        af0[1] = __float_as_uint(Ab[(g+8)  *ASTRIDE + k0 + tig    ]);
        af0[2] = __float_as_uint(Ab[ g     *ASTRIDE + k0 + tig + 4]);
        af0[3] = __float_as_uint(Ab[(g+8)  *ASTRIDE + k0 + tig + 4]);
        af1[0] = __float_as_uint(Ab[ g     *ASTRIDE + k0 + 8 + tig    ]);
        af1[1] = __float_as_uint(Ab[(g+8)  *ASTRIDE + k0 + 8 + tig    ]);
        af1[2] = __float_as_uint(Ab[ g     *ASTRIDE + k0 + 8 + tig + 4]);
        af1[3] = __float_as_uint(Ab[(g+8)  *ASTRIDE + k0 + 8 + tig + 4]);
        #pragma unroll
        for (int nt = 0; nt < 4; nt++){
            float4 w = ((const float4*)sWf)[((wt*4 + nt)*8 + kp)*32 + lane];
            mma8(acc[nt], af0, __float_as_uint(w.x), __float_as_uint(w.y));
            mma8(acc[nt], af1, __float_as_uint(w.z), __float_as_uint(w.w));
        }
    }
}

__device__ __forceinline__ void stage16(const float* __restrict__ src, float* __restrict__ Ab,
                                        int tt){
    const float4* s4 = (const float4*)src;
    #pragma unroll
    for (int rep = 0; rep < 4; rep++){
        int idx = tt + rep * 128;
        int row = idx >> 5, c4 = idx & 31;
        float4 v = s4[idx];
        *(float4*)(Ab + row * ASTRIDE + c4 * 4) = v;
    }
}

// ------------------------------------------------------------------ kernel 1
__global__ void __launch_bounds__(NTHREADS, 1) pre_kernel(
    const float* __restrict__ x,
    const float* __restrict__ ew1, const float* __restrict__ eb1,
    const float* __restrict__ nw1, const float* __restrict__ nb1)
{
    extern __shared__ float sm[];
    float* sW0 = sm;
    float* sW1 = sm + 16384;
    float* sW2 = sm + 32768;
    float* sB  = sm + 49152;    // eb1 | nb1
    float* sA  = sm + 49408;    // NTEAMS * 16*132

    const int tid = threadIdx.x;
    load_wfrag(ew1,         sW0, tid, NTHREADS);
    load_wfrag(ew1 + 16384, sW1, tid, NTHREADS);
    load_wfrag(nw1,         sW2, tid, NTHREADS);
    if (tid < 128){ sB[tid] = eb1[tid]; sB[128 + tid] = nb1[tid]; }
    __syncthreads();

    const int wid = tid >> 5, lane = tid & 31, team = wid >> 2, wt = wid & 3;
    const int g = lane >> 2, tig = lane & 3, tt = tid & 127, bid = 1 + team;
    float* Ab = sA + team * (16 * ASTRIDE);

    for (int tile = blockIdx.x * NTEAMS + team; tile < NODE_TTILES; tile += gridDim.x * NTEAMS){
        const int n0 = tile * 16;
        TBAR(bid);
        stage16(x + (size_t)n0 * 128, Ab, tt);
        TBAR(bid);
        const int rA = n0 + g, rB = n0 + g + 8;

        float acc[4][4];
        #pragma unroll
        for (int L = 0; L < 3; L++){
            gemm_layer(Ab, (L==0)?sW0:((L==1)?sW1:sW2), wt, lane, acc);
            float* dst = (L==0) ? g_Pa : ((L==1) ? g_Pb : g_Pn);
            const float* bias = (L==0) ? sB : ((L==2) ? sB + 128 : nullptr);
            #pragma unroll
            for (int nt = 0; nt < 4; nt++){
                int col = wt*32 + nt*8 + tig*2;
                float b0 = bias ? bias[col] : 0.f, b1 = bias ? bias[col+1] : 0.f;
                float2 oA = { acc[nt][0] + b0, acc[nt][1] + b1 };
                float2 oB = { acc[nt][2] + b0, acc[nt][3] + b1 };
                *(float2*)(dst + (size_t)rA * 128 + col) = oA;
                *(float2*)(dst + (size_t)rB * 128 + col) = oB;
            }
        }
    }
}

// ------------------------------------------------------------------ kernel 2
__global__ void __launch_bounds__(NTHREADS, 1) edge_kernel(
    const int* __restrict__ ei, const float* __restrict__ ea,
    const float* __restrict__ ew1, const float* __restrict__ ew2, const float* __restrict__ ew3,
    const float* __restrict__ eb2, const float* __restrict__ eb3,
    const float* __restrict__ elg, const float* __restrict__ elb,
    float* __restrict__ outE)
{
    extern __shared__ float sm[];
    float* sW1 = sm;
    float* sW2 = sm + 16384;
    float* sW3 = sm + 32768;
    float* sB  = sm + 49152;    // eb2 | eb3 | gamma | beta (512)
    float* sRed= sm + 49664;    // [384]: sum[192] | ssq[192]
    float* sA  = sm + 50048;

    const int tid = threadIdx.x;
    load_wfrag(ew1 + 32768, sW1, tid, NTHREADS);
    load_wfrag(ew2,         sW2, tid, NTHREADS);
    load_wfrag(ew3,         sW3, tid, NTHREADS);
    if (tid < 128){
        sB[tid] = eb2[tid]; sB[128+tid] = eb3[tid]; sB[256+tid] = elg[tid]; sB[384+tid] = elb[tid];
    }
    __syncthreads();

    const int wid = tid >> 5, lane = tid & 31, team = wid >> 2, wt = wid & 3;
    const int g = lane >> 2, tig = lane & 3, tt = tid & 127, bid = 1 + team;
    float* Ab = sA + team * (16 * ASTRIDE);

    for (int tile = blockIdx.x * NTEAMS + team; tile < EDGE_TTILES; tile += gridDim.x * NTEAMS){
        const int e0 = tile * 16;
        TBAR(bid);
        stage16(ea + (size_t)e0 * 128, Ab, tt);
        TBAR(bid);

        const int eA = e0 + g, eB = e0 + g + 8;
        const int viA = ei[eA], vjA = ei[NEDGE + eA];
        const int viB = ei[eB], vjB = ei[NEDGE + eB];

        float acc[4][4];
        // ---- layer 1: ea @ W1c, + Pa[i] + Pb[j], silu
        gemm_layer(Ab, sW1, wt, lane, acc);
        TBAR(bid);
        #pragma unroll
        for (int nt = 0; nt < 4; nt++){
            int col = wt*32 + nt*8 + tig*2;
            float2 paA = *(const float2*)(g_Pa + (size_t)viA*128 + col);
            float2 pbA = *(const float2*)(g_Pb + (size_t)vjA*128 + col);
            float2 paB = *(const float2*)(g_Pa + (size_t)viB*128 + col);
            float2 pbB = *(const float2*)(g_Pb + (size_t)vjB*128 + col);
            float2 wA = { __uint_as_float(f2tf(sigl(acc[nt][0] + paA.x + pbA.x))),
                          __uint_as_float(f2tf(sigl(acc[nt][1] + paA.y + pbA.y))) };
            float2 wB = { __uint_as_float(f2tf(sigl(acc[nt][2] + paB.x + pbB.x))),
                          __uint_as_float(f2tf(sigl(acc[nt][3] + paB.y + pbB.y))) };
            *(float2*)(Ab +  g   *ASTRIDE + col) = wA;
            *(float2*)(Ab + (g+8)*ASTRIDE + col) = wB;
        }
        TBAR(bid);
        // ---- layer 2: + eb2, silu
        gemm_layer(Ab, sW2, wt, lane, acc);
        TBAR(bid);
        #pragma unroll
        for (int nt = 0; nt < 4; nt++){
            int col = wt*32 + nt*8 + tig*2;
            float b0 = sB[col], b1 = sB[col+1];
            float2 wA = { __uint_as_float(f2tf(sigl(acc[nt][0] + b0))),
                          __uint_as_float(f2tf(sigl(acc[nt][1] + b1))) };
            float2 wB = { __uint_as_float(f2tf(sigl(acc[nt][2] + b0))),
                          __uint_as_float(f2tf(sigl(acc[nt][3] + b1))) };
            *(float2*)(Ab +  g   *ASTRIDE + col) = wA;
            *(float2*)(Ab + (g+8)*ASTRIDE + col) = wB;
        }
        TBAR(bid);
        // ---- layer 3: + eb3, LN, residual, scatter
        gemm_layer(Ab, sW3, wt, lane, acc);
        float s0=0.f,q0=0.f,s1=0.f,q1=0.f;
        #pragma unroll
        for (int nt = 0; nt < 4; nt++){
            int col = wt*32 + nt*8 + tig*2;
            acc[nt][0] += sB[128+col]; acc[nt][1] += sB[128+col+1];
            acc[nt][2] += sB[128+col]; acc[nt][3] += sB[128+col+1];
            s0 += acc[nt][0]+acc[nt][1]; q0 += acc[nt][0]*acc[nt][0]+acc[nt][1]*acc[nt][1];
            s1 += acc[nt][2]+acc[nt][3]; q1 += acc[nt][2]*acc[nt][2]+acc[nt][3]*acc[nt][3];
        }
        #pragma unroll
        for (int o = 1; o < 4; o <<= 1){
            s0 += __shfl_xor_sync(0xffffffffu, s0, o);
            q0 += __shfl_xor_sync(0xffffffffu, q0, o);
            s1 += __shfl_xor_sync(0xffffffffu, s1, o);
            q1 += __shfl_xor_sync(0xffffffffu, q1, o);
        }
        if (tig == 0){
            int ib = team*64 + wt*16;
            sRed[ib+g] = s0; sRed[ib+g+8] = s1;
            sRed[192+ib+g] = q0; sRed[192+ib+g+8] = q1;
        }
        TBAR(bid);
        float sumA=0.f,sqA=0.f,sumB=0.f,sqB=0.f;
        #pragma unroll
        for (int w2 = 0; w2 < 4; w2++){
            int ib = team*64 + w2*16;
            sumA += sRed[ib+g];   sqA += sRed[192+ib+g];
            sumB += sRed[ib+g+8]; sqB += sRed[192+ib+g+8];
        }
        float mA = sumA*(1.f/128.f), iA = rsqrtf(sqA*(1.f/128.f) - mA*mA + EPS_LN);
        float mB = sumB*(1.f/128.f), iB = rsqrtf(sqB*(1.f/128.f) - mB*mB + EPS_LN);
        #pragma unroll
        for (int nt = 0; nt < 4; nt++){
            int col = wt*32 + nt*8 + tig*2;
            float gm0 = sB[256+col], gm1 = sB[256+col+1];
            float bt0 = sB[384+col], bt1 = sB[384+col+1];
            float2 rA = *(const float2*)(ea + (size_t)eA*128 + col);
            float2 rB = *(const float2*)(ea + (size_t)eB*128 + col);
            float2 oA = { rA.x + (acc[nt][0]-mA)*iA*gm0 + bt0,
                          rA.y + (acc[nt][1]-mA)*iA*gm1 + bt1 };
            float2 oB = { rB.x + (acc[nt][2]-mB)*iB*gm0 + bt0,
                          rB.y + (acc[nt][3]-mB)*iB*gm1 + bt1 };
            *(float2*)(outE + (size_t)eA*128 + col) = oA;
            *(float2*)(outE + (size_t)eB*128 + col) = oB;
            asm volatile("red.global.add.v2.f32 [%0], {%1,%2};"
                         :: "l"(g_agg + (size_t)vjA*128 + col), "f"(oA.x), "f"(oA.y) : "memory");
            asm volatile("red.global.add.v2.f32 [%0], {%1,%2};"
                         :: "l"(g_agg + (size_t)vjB*128 + col), "f"(oB.x), "f"(oB.y) : "memory");
        }
    }
}

// ------------------------------------------------------------------ kernel 3
__global__ void __launch_bounds__(NTHREADS, 1) node_kernel(
    const float* __restrict__ x,
    const float* __restrict__ nw1, const float* __restrict__ nw2, const float* __restrict__ nw3,
    const float* __restrict__ nb2, const float* __restrict__ nb3,
    const float* __restrict__ nlg, const float* __restrict__ nlb,
    float* __restrict__ outX)
{
    extern __shared__ float sm[];
    float* sW1 = sm;
    float* sW2 = sm + 16384;
    float* sW3 = sm + 32768;
    float* sB  = sm + 49152;
    float* sRed= sm + 49664;
    float* sA  = sm + 50048;

    const int tid = threadIdx.x;
    load_wfrag(nw1 + 16384, sW1, tid, NTHREADS);
    load_wfrag(nw2,         sW2, tid, NTHREADS);
    load_wfrag(nw3,         sW3, tid, NTHREADS);
    if (tid < 128){
        sB[tid] = nb2[tid]; sB[128+tid] = nb3[tid]; sB[256+tid] = nlg[tid]; sB[384+tid] = nlb[tid];
    }
    __syncthreads();

    const int wid = tid >> 5, lane = tid & 31, team = wid >> 2, wt = wid & 3;
    const int g = lane >> 2, tig = lane & 3, tt = tid & 127, bid = 1 + team;
    float* Ab = sA + team * (16 * ASTRIDE);

    for (int tile = blockIdx.x * NTEAMS + team; tile < NODE_TTILES; tile += gridDim.x * NTEAMS){
        const int n0 = tile * 16;
        TBAR(bid);
        stage16(g_agg + (size_t)n0 * 128, Ab, tt);
        TBAR(bid);
        const int rA = n0 + g, rB = n0 + g + 8;

        float acc[4][4];
        gemm_layer(Ab, sW1, wt, lane, acc);
        TBAR(bid);
        #pragma unroll
        for (int nt = 0; nt < 4; nt++){
            int col = wt*32 + nt*8 + tig*2;
            float2 pnA = *(const float2*)(g_Pn + (size_t)rA*128 + col);
            float2 pnB = *(const float2*)(g_Pn + (size_t)rB*128 + col);
            float2 wA = { __uint_as_float(f2tf(sigl(acc[nt][0] + pnA.x))),
                          __uint_as_float(f2tf(sigl(acc[nt][1] + pnA.y))) };
            float2 wB = { __uint_as_float(f2tf(sigl(acc[nt][2] + pnB.x))),
                          __uint_as_float(f2tf(sigl(acc[nt][3] + pnB.y))) };
            *(float2*)(Ab +  g   *ASTRIDE + col) = wA;
            *(float2*)(Ab + (g+8)*ASTRIDE + col) = wB;
        }
        TBAR(bid);
        gemm_layer(Ab, sW2, wt, lane, acc);
        TBAR(bid);
        #pragma unroll
        for (int nt = 0; nt < 4; nt++){
            int col = wt*32 + nt*8 + tig*2;
            float b0 = sB[col], b1 = sB[col+1];
            float2 wA = { __uint_as_float(f2tf(sigl(acc[nt][0] + b0))),
                          __uint_as_float(f2tf(sigl(acc[nt][1] + b1))) };
            float2 wB = { __uint_as_float(f2tf(sigl(acc[nt][2] + b0))),
                          __uint_as_float(f2tf(sigl(acc[nt][3] + b1))) };
            *(float2*)(Ab +  g   *ASTRIDE + col) = wA;
            *(float2*)(Ab + (g+8)*ASTRIDE + col) = wB;
        }
        TBAR(bid);
        gemm_layer(Ab, sW3, wt, lane, acc);
        float s0=0.f,q0=0.f,s1=0.f,q1=0.f;
        #pragma unroll
        for (int nt = 0; nt < 4; nt++){
            int col = wt*32 + nt*8 + tig*2;
            acc[nt][0] += sB[128+col]; acc[nt][1] += sB[128+col+1];
            acc[nt][2] += sB[128+col]; acc[nt][3] += sB[128+col+1];
            s0 += acc[nt][0]+acc[nt][1]; q0 += acc[nt][0]*acc[nt][0]+acc[nt][1]*acc[nt][1];
            s1 += acc[nt][2]+acc[nt][3]; q1 += acc[nt][2]*acc[nt][2]+acc[nt][3]*acc[nt][3];
        }
        #pragma unroll
        for (int o = 1; o < 4; o <<= 1){
            s0 += __shfl_xor_sync(0xffffffffu, s0, o);
            q0 += __shfl_xor_sync(0xffffffffu, q0, o);
            s1 += __shfl_xor_sync(0xffffffffu, s1, o);
            q1 += __shfl_xor_sync(0xffffffffu, q1, o);
        }
        if (tig == 0){
            int ib = team*64 + wt*16;
            sRed[ib+g] = s0; sRed[ib+g+8] = s1;
            sRed[192+ib+g] = q0; sRed[192+ib+g+8] = q1;
        }
        TBAR(bid);
        float sumA=0.f,sqA=0.f,sumB=0.f,sqB=0.f;
        #pragma unroll
        for (int w2 = 0; w2 < 4; w2++){
            int ib = team*64 + w2*16;
            sumA += sRed[ib+g];   sqA += sRed[192+ib+g];
            sumB += sRed[ib+g+8]; sqB += sRed[192+ib+g+8];
        }
        float mA = sumA*(1.f/128.f), iA = rsqrtf(sqA*(1.f/128.f) - mA*mA + EPS_LN);
        float mB = sumB*(1.f/128.f), iB = rsqrtf(sqB*(1.f/128.f) - mB*mB + EPS_LN);
        #pragma unroll
        for (int nt = 0; nt < 4; nt++){
            int col = wt*32 + nt*8 + tig*2;
            float gm0 = sB[256+col], gm1 = sB[256+col+1];
            float bt0 = sB[384+col], bt1 = sB[384+col+1];
            float2 rxA = *(const float2*)(x + (size_t)rA*128 + col);
            float2 rxB = *(const float2*)(x + (size_t)rB*128 + col);
            float2 oA = { rxA.x + (acc[nt][0]-mA)*iA*gm0 + bt0,
                          rxA.y + (acc[nt][1]-mA)*iA*gm1 + bt1 };
            float2 oB = { rxB.x + (acc[nt][2]-mB)*iB*gm0 + bt0,
                          rxB.y + (acc[nt][3]-mB)*iB*gm1 + bt1 };
            *(float2*)(outX + (size_t)rA*128 + col) = oA;
            *(float2*)(outX + (size_t)rB*128 + col) = oB;
        }
    }
}

// ------------------------------------------------------------------ host
extern "C" void kernel_launch(void* const* d_in, const int* in_sizes, int n_in,
                              void* d_out, int out_size) {
    const float* x   = (const float*)d_in[0];
    const int*   ei  = (const int*)  d_in[1];
    const float* ea  = (const float*)d_in[2];
    const float* ew1 = (const float*)d_in[3];
    const float* eb1 = (const float*)d_in[4];
    const float* ew2 = (const float*)d_in[5];
    const float* eb2 = (const float*)d_in[6];
    const float* ew3 = (const float*)d_in[7];
    const float* eb3 = (const float*)d_in[8];
    const float* elg = (const float*)d_in[9];
    const float* elb = (const float*)d_in[10];
    const float* nw1 = (const float*)d_in[11];
    const float* nb1 = (const float*)d_in[12];
    const float* nw2 = (const float*)d_in[13];
    const float* nb2 = (const float*)d_in[14];
    const float* nw3 = (const float*)d_in[15];
    const float* nb3 = (const float*)d_in[16];
    const float* nlg = (const float*)d_in[17];
    const float* nlb = (const float*)d_in[18];

    float* outX = (float*)d_out;
    float* outE = outX + (size_t)NNODE * 128;

    // floats: pre = 49152+256+3*2112 = 55744 ; edge/node = 49152+512+384+3*2112 = 56384
    const size_t smem_pre  = 55744u * 4u;   // 222976
    const size_t smem_main = 56384u * 4u;   // 225536
    cudaFuncSetAttribute(pre_kernel,  cudaFuncAttributeMaxDynamicSharedMemorySize, (int)smem_pre);
    cudaFuncSetAttribute(edge_kernel, cudaFuncAttributeMaxDynamicSharedMemorySize, (int)smem_main);
    cudaFuncSetAttribute(node_kernel, cudaFuncAttributeMaxDynamicSharedMemorySize, (int)smem_main);

    void* aggp = nullptr;
    cudaGetSymbolAddress(&aggp, g_agg);
    cudaMemsetAsync(aggp, 0, sizeof(float) * (size_t)NNODE * 128, 0);

    pre_kernel<<<152, NTHREADS, smem_pre>>>(x, ew1, eb1, nw1, nb1);
    edge_kernel<<<152, NTHREADS, smem_main>>>(ei, ea, ew1, ew2, ew3, eb2, eb3, elg, elb, outE);
    node_kernel<<<152, NTHREADS, smem_main>>>(x, nw1, nw2, nw3, nb2, nb3, nlg, nlb, outX);
}